// round 1
// baseline (speedup 1.0000x reference)
#include <cuda_runtime.h>
#include <cuda_bf16.h>
#include <cstdint>

// Problem constants (fixed shapes per reference)
#define N0 50000
#define N1 150000
#define N2 20000
#define N3 5000
#define N4 1000
#define E0 800000
#define E1 1500000
#define NNZ01 300000
#define DIM 64

#define N0D (N0*DIM)            // 3,200,000
#define N1D (N1*DIM)            // 9,600,000

// Scratch (device globals: allocation-free)
__device__ float g_m[2*(N0D + N1D)];    // [m0 | mt | m1 | ms]
__device__ float g_acc[2*(N0D + N1D)];  // [s00 | s10 | s11 | s01]
__device__ float g_coef[E0 + E1];

// ---------------------------------------------------------------------------
// zero accumulators
__global__ void zero_kernel(float* __restrict__ p, int n4) {
    int i = blockIdx.x * blockDim.x + threadIdx.x;
    if (i < n4) ((float4*)p)[i] = make_float4(0.f, 0.f, 0.f, 0.f);
}

// ---------------------------------------------------------------------------
// coef[e] = val[e] * dot(cci[e], a)   for both adjacency edge sets
__global__ void coef_kernel(const float* __restrict__ val0, const float* __restrict__ cci0,
                            const float* __restrict__ a0,
                            const float* __restrict__ val1, const float* __restrict__ cci1,
                            const float* __restrict__ a1,
                            float* __restrict__ coef) {
    int e = blockIdx.x * blockDim.x + threadIdx.x;
    if (e < E0) {
        const float* c = cci0 + (size_t)e * 3;
        coef[e] = val0[e] * (c[0]*a0[0] + c[1]*a0[1] + c[2]*a0[2]);
    } else if (e < E0 + E1) {
        int f = e - E0;
        const float* c = cci1 + (size_t)f * 3;
        coef[e] = val1[f] * (c[0]*a1[0] + c[1]*a1[1] + c[2]*a1[2]);
    }
}

// ---------------------------------------------------------------------------
// Dual GEMM: outA = x @ WA, outB = x @ WB    (x: nrows x 64, W: 64x64)
// 128 threads, 32-row tiles, grid-stride over tiles. Register-blocked 4x4 per
// thread per output matrix. W matrices resident in smem for block lifetime.
__global__ void __launch_bounds__(128) gemm_dual_kernel(
    const float* __restrict__ x, const float* __restrict__ WA, const float* __restrict__ WB,
    float* __restrict__ outA, float* __restrict__ outB, int nrows)
{
    __shared__ float sWA[64*64];
    __shared__ float sWB[64*64];
    __shared__ float sXT[64][36];   // [k][row], padded; 36%4==0 keeps float4 alignment

    int tid = threadIdx.x;
    for (int i = tid*4; i < 4096; i += 128*4) {
        *(float4*)&sWA[i] = *(const float4*)&WA[i];
        *(float4*)&sWB[i] = *(const float4*)&WB[i];
    }
    int ntiles = (nrows + 31) >> 5;
    int tx = tid & 15;      // 4 cols each
    int ty = tid >> 4;      // 0..7 -> 4 rows each (32 rows)

    for (int tile = blockIdx.x; tile < ntiles; tile += gridDim.x) {
        int row0 = tile << 5;
        __syncthreads();
        #pragma unroll
        for (int i = 0; i < 4; i++) {
            int q  = tid + i*128;            // 512 quads
            int r  = q >> 4;                 // 0..31
            int c4 = (q & 15) << 2;
            float4 v = make_float4(0.f,0.f,0.f,0.f);
            if (row0 + r < nrows) v = *(const float4*)&x[(size_t)(row0 + r)*DIM + c4];
            sXT[c4+0][r] = v.x; sXT[c4+1][r] = v.y; sXT[c4+2][r] = v.z; sXT[c4+3][r] = v.w;
        }
        __syncthreads();

        float aA[4][4] = {}; float aB[4][4] = {};
        #pragma unroll
        for (int k = 0; k < 64; k++) {
            float4 xv = *(float4*)&sXT[k][ty*4];
            float4 wa = *(float4*)&sWA[k*64 + tx*4];
            float4 wb = *(float4*)&sWB[k*64 + tx*4];
            float xr[4]  = {xv.x, xv.y, xv.z, xv.w};
            float wac[4] = {wa.x, wa.y, wa.z, wa.w};
            float wbc[4] = {wb.x, wb.y, wb.z, wb.w};
            #pragma unroll
            for (int r = 0; r < 4; r++)
                #pragma unroll
                for (int c = 0; c < 4; c++) {
                    aA[r][c] += xr[r]*wac[c];
                    aB[r][c] += xr[r]*wbc[c];
                }
        }
        #pragma unroll
        for (int r = 0; r < 4; r++) {
            int row = row0 + ty*4 + r;
            if (row < nrows) {
                *(float4*)&outA[(size_t)row*DIM + tx*4] =
                    make_float4(aA[r][0], aA[r][1], aA[r][2], aA[r][3]);
                *(float4*)&outB[(size_t)row*DIM + tx*4] =
                    make_float4(aB[r][0], aB[r][1], aB[r][2], aB[r][3]);
            }
        }
    }
}

// ---------------------------------------------------------------------------
// Edge scatter: acc[dst[e]] += coef[e] * m[src[e]]   (64 floats per edge)
// Half-warp (16 threads) per edge; each thread handles one float4 lane and
// issues a single vector reduction (red.global.add.v4.f32).
__global__ void __launch_bounds__(256) scatter_kernel(
    const int* __restrict__ src, const int* __restrict__ dst,
    const float* __restrict__ coef, const float* __restrict__ m,
    float* __restrict__ acc, int E)
{
    int t = blockIdx.x * blockDim.x + threadIdx.x;
    int e = t >> 4;
    if (e >= E) return;
    int lane4 = (t & 15) << 2;

    float c = __ldg(&coef[e]);
    int s = __ldg(&src[e]);
    int d = __ldg(&dst[e]);

    float4 v = *(const float4*)&m[(size_t)s*DIM + lane4];
    float4 r = make_float4(v.x*c, v.y*c, v.z*c, v.w*c);
    float* p = &acc[(size_t)d*DIM + lane4];
    asm volatile("red.global.add.v4.f32 [%0], {%1, %2, %3, %4};"
                 :: "l"(p), "f"(r.x), "f"(r.y), "f"(r.z), "f"(r.w)
                 : "memory");
}

// ---------------------------------------------------------------------------
// Epilogue: out = relu( (relu(sA)+relu(sB)) @ W )
// 256 threads, 64-row tiles, grid-stride over tiles.
__global__ void __launch_bounds__(256) aggr_kernel(
    const float* __restrict__ inA, const float* __restrict__ inB,
    const float* __restrict__ W, float* __restrict__ out, int nrows)
{
    __shared__ float sW[64*64];
    __shared__ float sXT[64][68];   // 68%4==0 keeps float4 alignment

    int tid = threadIdx.x;
    for (int i = tid*4; i < 4096; i += 256*4)
        *(float4*)&sW[i] = *(const float4*)&W[i];

    int ntiles = (nrows + 63) >> 6;
    int tx = tid & 15;   // 4 cols
    int ty = tid >> 4;   // 0..15 -> 4 rows each (64 rows)

    for (int tile = blockIdx.x; tile < ntiles; tile += gridDim.x) {
        int row0 = tile << 6;
        __syncthreads();
        #pragma unroll
        for (int i = 0; i < 4; i++) {
            int q  = tid + i*256;            // 1024 quads
            int r  = q >> 4;                 // 0..63
            int c4 = (q & 15) << 2;
            float4 v = make_float4(0.f,0.f,0.f,0.f);
            if (row0 + r < nrows) {
                size_t off = (size_t)(row0 + r)*DIM + c4;
                float4 a = *(const float4*)&inA[off];
                float4 b = *(const float4*)&inB[off];
                v.x = fmaxf(a.x,0.f) + fmaxf(b.x,0.f);
                v.y = fmaxf(a.y,0.f) + fmaxf(b.y,0.f);
                v.z = fmaxf(a.z,0.f) + fmaxf(b.z,0.f);
                v.w = fmaxf(a.w,0.f) + fmaxf(b.w,0.f);
            }
            sXT[c4+0][r] = v.x; sXT[c4+1][r] = v.y; sXT[c4+2][r] = v.z; sXT[c4+3][r] = v.w;
        }
        __syncthreads();

        float acc4[4][4] = {};
        #pragma unroll
        for (int k = 0; k < 64; k++) {
            float4 xv = *(float4*)&sXT[k][ty*4];
            float4 w  = *(float4*)&sW[k*64 + tx*4];
            float xr[4] = {xv.x, xv.y, xv.z, xv.w};
            float wc[4] = {w.x, w.y, w.z, w.w};
            #pragma unroll
            for (int r = 0; r < 4; r++)
                #pragma unroll
                for (int c = 0; c < 4; c++)
                    acc4[r][c] += xr[r]*wc[c];
        }
        #pragma unroll
        for (int r = 0; r < 4; r++) {
            int row = row0 + ty*4 + r;
            if (row < nrows) {
                *(float4*)&out[(size_t)row*DIM + tx*4] =
                    make_float4(fmaxf(acc4[r][0],0.f), fmaxf(acc4[r][1],0.f),
                                fmaxf(acc4[r][2],0.f), fmaxf(acc4[r][3],0.f));
            }
        }
    }
}

// ---------------------------------------------------------------------------
extern "C" void kernel_launch(void* const* d_in, const int* in_sizes, int n_in,
                              void* d_out, int out_size) {
    const float* x0    = (const float*)d_in[0];
    const float* x1    = (const float*)d_in[1];
    const float* x2    = (const float*)d_in[2];
    const float* x3    = (const float*)d_in[3];
    const float* x4    = (const float*)d_in[4];
    const int*   adj0  = (const int*)  d_in[5];    // (2, E0)
    const float* adj0v = (const float*)d_in[6];
    const int*   adj1  = (const int*)  d_in[7];    // (2, E1)
    const float* adj1v = (const float*)d_in[8];
    const int*   inc   = (const int*)  d_in[9];    // (2, NNZ01) [row; col]
    const float* incv  = (const float*)d_in[10];
    const float* cci0  = (const float*)d_in[11];
    const float* cci1  = (const float*)d_in[12];
    const float* Whbs0 = (const float*)d_in[13];
    const float* a0    = (const float*)d_in[14];
    const float* Whbs1 = (const float*)d_in[15];
    const float* a1    = (const float*)d_in[16];
    const float* Ws    = (const float*)d_in[17];   // W_hbns_s
    const float* Wt    = (const float*)d_in[18];   // W_hbns_t
    const float* Wag0  = (const float*)d_in[19];
    const float* Wag1  = (const float*)d_in[20];
    float* out = (float*)d_out;

    float *pm, *pa, *pc;
    cudaGetSymbolAddress((void**)&pm, g_m);
    cudaGetSymbolAddress((void**)&pa, g_acc);
    cudaGetSymbolAddress((void**)&pc, g_coef);

    float* pm0 = pm;                  // x_0 @ W_hbs0
    float* pmt = pm + N0D;            // x_0 @ W_hbns_t
    float* pm1 = pm + 2*(size_t)N0D;  // x_1 @ W_hbs1
    float* pms = pm + 2*(size_t)N0D + N1D; // x_1 @ W_hbns_s

    float* s00 = pa;
    float* s10 = pa + N0D;
    float* s11 = pa + 2*(size_t)N0D;
    float* s01 = pa + 2*(size_t)N0D + N1D;

    // 1) zero accumulators
    int nz4 = 2*(N0D + N1D) / 4;
    zero_kernel<<<(nz4 + 255)/256, 256>>>(pa, nz4);

    // 2) edge coefficients for both adjacency sets
    coef_kernel<<<((E0 + E1) + 255)/256, 256>>>(adj0v, cci0, a0, adj1v, cci1, a1, pc);

    // 3) dense projections (dual GEMMs, x read once per pair)
    gemm_dual_kernel<<<740, 128>>>(x0, Whbs0, Wt, pm0, pmt, N0);
    gemm_dual_kernel<<<740, 128>>>(x1, Whbs1, Ws, pm1, pms, N1);

    // 4) edge scatters (vectorized global reductions)
    scatter_kernel<<<((size_t)E0*16 + 255)/256, 256>>>(adj0,       adj0 + E0,  pc,      pm0, s00, E0);
    scatter_kernel<<<((size_t)E1*16 + 255)/256, 256>>>(adj1,       adj1 + E1,  pc + E0, pm1, s11, E1);
    scatter_kernel<<<((size_t)NNZ01*16 + 255)/256, 256>>>(inc + NNZ01, inc,        incv, pms, s10, NNZ01);
    scatter_kernel<<<((size_t)NNZ01*16 + 255)/256, 256>>>(inc,         inc + NNZ01, incv, pmt, s01, NNZ01);

    // 5) fused relu-add-GEMM-relu epilogues, straight into d_out
    aggr_kernel<<<(N0 + 63)/64, 256>>>(s00, s10, Wag0, out, N0);
    aggr_kernel<<<(N1 + 63)/64, 256>>>(s11, s01, Wag1, out + (size_t)N0*DIM, N1);

    // 6) passthrough outputs
    size_t off2 = (size_t)(N0 + N1)*DIM;
    size_t off3 = off2 + (size_t)N2*DIM;
    size_t off4 = off3 + (size_t)N3*DIM;
    cudaMemcpyAsync(out + off2, x2, (size_t)N2*DIM*sizeof(float), cudaMemcpyDeviceToDevice, 0);
    cudaMemcpyAsync(out + off3, x3, (size_t)N3*DIM*sizeof(float), cudaMemcpyDeviceToDevice, 0);
    cudaMemcpyAsync(out + off4, x4, (size_t)N4*DIM*sizeof(float), cudaMemcpyDeviceToDevice, 0);
}

// round 3
// speedup vs baseline: 1.1645x; 1.1645x over previous
#include <cuda_runtime.h>
#include <cuda_bf16.h>
#include <cstdint>

// Problem constants (fixed shapes per reference)
#define N0 50000
#define N1 150000
#define N2 20000
#define N3 5000
#define N4 1000
#define E0 800000
#define E1 1500000
#define NNZ01 300000
#define DIM 64

#define N0D (N0*DIM)            // 3,200,000
#define N1D (N1*DIM)            // 9,600,000

#define ET   (E0 + E1 + 2*NNZ01)     // 2,900,000 total binned edges
#define NCNT (2*(N0 + N1))           // 400,000 destination counters
// bucket bases inside the counter space:
//   b0: adj0   -> N0 nodes   @ 0
//   b1: adj1   -> N1 nodes   @ N0
//   b2: inc->0 -> N0 nodes   @ N0+N1
//   b3: inc->1 -> N1 nodes   @ N0+N1+N0
#define B0 0
#define B1 (N0)
#define B2 (N0+N1)
#define B3 (N0+N1+N0)

#define SCAN_BLK 1024
#define NB ((NCNT + SCAN_BLK - 1)/SCAN_BLK)   // 391

// -------------------------- device scratch (no allocs) ---------------------
__device__ float g_m[2*(N0D + N1D)];        // [m0 | mt | m1 | ms]  102MB
__device__ float g_sum[N0D + N1D];          // relu-sums per node   51MB
__device__ float g_coef[E0 + E1];
__device__ int   g_cnt[NCNT];
__device__ int   g_cur[NCNT];
__device__ int   g_offs[NCNT + 1];
__device__ int   g_bsums[NB + 1];
__device__ int2  g_rec[ET];                 // {src, coef-as-int}   23MB

// ---------------------------------------------------------------------------
__global__ void zero_cnt_kernel() {
    int i = blockIdx.x * blockDim.x + threadIdx.x;
    if (i < NCNT) { g_cnt[i] = 0; g_cur[i] = 0; }
}

// coef[e] = val[e] * dot(cci[e], a)   for both adjacency edge sets
__global__ void coef_kernel(const float* __restrict__ val0, const float* __restrict__ cci0,
                            const float* __restrict__ a0,
                            const float* __restrict__ val1, const float* __restrict__ cci1,
                            const float* __restrict__ a1) {
    int e = blockIdx.x * blockDim.x + threadIdx.x;
    if (e < E0) {
        const float* c = cci0 + (size_t)e * 3;
        g_coef[e] = val0[e] * (c[0]*a0[0] + c[1]*a0[1] + c[2]*a0[2]);
    } else if (e < E0 + E1) {
        int f = e - E0;
        const float* c = cci1 + (size_t)f * 3;
        g_coef[e] = val1[f] * (c[0]*a1[0] + c[1]*a1[1] + c[2]*a1[2]);
    }
}

// histogram destinations
__global__ void count_kernel(const int* __restrict__ adj0, const int* __restrict__ adj1,
                             const int* __restrict__ inc) {
    int t = blockIdx.x * blockDim.x + threadIdx.x;
    if (t >= ET) return;
    int ci;
    if (t < E0)                   ci = B0 + __ldg(&adj0[E0 + t]);
    else if (t < E0 + E1)         ci = B1 + __ldg(&adj1[E1 + (t - E0)]);
    else if (t < E0 + E1 + NNZ01) ci = B2 + __ldg(&inc[t - (E0 + E1)]);          // row
    else                          ci = B3 + __ldg(&inc[NNZ01 + (t - (E0+E1+NNZ01))]); // col
    atomicAdd(&g_cnt[ci], 1);
}

// --- 3-pass exclusive scan over g_cnt[NCNT] -> g_offs ---
__global__ void scan_pass1() {   // 256 thr, 1024 elems/block -> block sums
    __shared__ int wsum[8];
    int tid = threadIdx.x, lane = tid & 31, wid = tid >> 5;
    int base = blockIdx.x * SCAN_BLK + tid * 4;
    int4 v = make_int4(0,0,0,0);
    if (base < NCNT) v = *(const int4*)&g_cnt[base];     // NCNT % 4 == 0
    int s = v.x + v.y + v.z + v.w;
    #pragma unroll
    for (int o = 16; o; o >>= 1) s += __shfl_down_sync(0xffffffffu, s, o);
    if (lane == 0) wsum[wid] = s;
    __syncthreads();
    if (tid == 0) {
        int tot = 0;
        #pragma unroll
        for (int i = 0; i < 8; i++) tot += wsum[i];
        g_bsums[blockIdx.x] = tot;
    }
}

__global__ void scan_pass2() {   // 1 block, 512 thr: exclusive scan of NB sums
    __shared__ int sm[512];
    int t = threadIdx.x;
    int v = (t < NB) ? g_bsums[t] : 0;
    sm[t] = v;
    __syncthreads();
    #pragma unroll
    for (int o = 1; o < 512; o <<= 1) {
        int add = (t >= o) ? sm[t - o] : 0;
        __syncthreads();
        sm[t] += add;
        __syncthreads();
    }
    if (t < NB) g_bsums[t] = sm[t] - v;   // exclusive
    if (t == 0) g_offs[NCNT] = ET;
}

__global__ void scan_pass3() {   // per-block exclusive scan + block offset
    __shared__ int woff[8];
    int tid = threadIdx.x, lane = tid & 31, wid = tid >> 5;
    int base = blockIdx.x * SCAN_BLK + tid * 4;
    int4 v = make_int4(0,0,0,0);
    if (base < NCNT) v = *(const int4*)&g_cnt[base];
    int s = v.x + v.y + v.z + v.w;
    int incl = s;
    #pragma unroll
    for (int o = 1; o < 32; o <<= 1) {
        int n = __shfl_up_sync(0xffffffffu, incl, o);
        if (lane >= o) incl += n;
    }
    if (lane == 31) woff[wid] = incl;
    __syncthreads();
    if (tid == 0) {
        int acc = 0;
        #pragma unroll
        for (int i = 0; i < 8; i++) { int t2 = woff[i]; woff[i] = acc; acc += t2; }
    }
    __syncthreads();
    int excl = incl - s + woff[wid] + g_bsums[blockIdx.x];
    if (base < NCNT) {
        g_offs[base]     = excl;
        g_offs[base + 1] = excl + v.x;
        g_offs[base + 2] = excl + v.x + v.y;
        g_offs[base + 3] = excl + v.x + v.y + v.z;
    }
}

// scatter edge records into buckets
__global__ void fill_kernel(const int* __restrict__ adj0, const int* __restrict__ adj1,
                            const int* __restrict__ inc, const float* __restrict__ incv) {
    int t = blockIdx.x * blockDim.x + threadIdx.x;
    if (t >= ET) return;
    int ci, src; float coef;
    if (t < E0) {
        ci   = B0 + __ldg(&adj0[E0 + t]);
        src  = __ldg(&adj0[t]);
        coef = g_coef[t];
    } else if (t < E0 + E1) {
        int f = t - E0;
        ci   = B1 + __ldg(&adj1[E1 + f]);
        src  = __ldg(&adj1[f]);
        coef = g_coef[E0 + f];
    } else if (t < E0 + E1 + NNZ01) {
        int f = t - (E0 + E1);
        ci   = B2 + __ldg(&inc[f]);           // dst = row (N0)
        src  = __ldg(&inc[NNZ01 + f]);        // src = col (N1)
        coef = __ldg(&incv[f]);
    } else {
        int f = t - (E0 + E1 + NNZ01);
        ci   = B3 + __ldg(&inc[NNZ01 + f]);   // dst = col (N1)
        src  = __ldg(&inc[f]);                // src = row (N0)
        coef = __ldg(&incv[f]);
    }
    int pos = g_offs[ci] + atomicAdd(&g_cur[ci], 1);
    g_rec[pos] = make_int2(src, __float_as_int(coef));
}

// ---------------------------------------------------------------------------
// Dual GEMM: outA = x @ WA, outB = x @ WB
__global__ void __launch_bounds__(128) gemm_dual_kernel(
    const float* __restrict__ x, const float* __restrict__ WA, const float* __restrict__ WB,
    float* __restrict__ outA, float* __restrict__ outB, int nrows)
{
    __shared__ float sWA[64*64];
    __shared__ float sWB[64*64];
    __shared__ float sXT[64][36];

    int tid = threadIdx.x;
    for (int i = tid*4; i < 4096; i += 128*4) {
        *(float4*)&sWA[i] = *(const float4*)&WA[i];
        *(float4*)&sWB[i] = *(const float4*)&WB[i];
    }
    int ntiles = (nrows + 31) >> 5;
    int tx = tid & 15;
    int ty = tid >> 4;

    for (int tile = blockIdx.x; tile < ntiles; tile += gridDim.x) {
        int row0 = tile << 5;
        __syncthreads();
        #pragma unroll
        for (int i = 0; i < 4; i++) {
            int q  = tid + i*128;
            int r  = q >> 4;
            int c4 = (q & 15) << 2;
            float4 v = make_float4(0.f,0.f,0.f,0.f);
            if (row0 + r < nrows) v = *(const float4*)&x[(size_t)(row0 + r)*DIM + c4];
            sXT[c4+0][r] = v.x; sXT[c4+1][r] = v.y; sXT[c4+2][r] = v.z; sXT[c4+3][r] = v.w;
        }
        __syncthreads();

        float aA[4][4] = {}; float aB[4][4] = {};
        #pragma unroll
        for (int k = 0; k < 64; k++) {
            float4 xv = *(float4*)&sXT[k][ty*4];
            float4 wa = *(float4*)&sWA[k*64 + tx*4];
            float4 wb = *(float4*)&sWB[k*64 + tx*4];
            float xr[4]  = {xv.x, xv.y, xv.z, xv.w};
            float wac[4] = {wa.x, wa.y, wa.z, wa.w};
            float wbc[4] = {wb.x, wb.y, wb.z, wb.w};
            #pragma unroll
            for (int r = 0; r < 4; r++)
                #pragma unroll
                for (int c = 0; c < 4; c++) {
                    aA[r][c] += xr[r]*wac[c];
                    aB[r][c] += xr[r]*wbc[c];
                }
        }
        #pragma unroll
        for (int r = 0; r < 4; r++) {
            int row = row0 + ty*4 + r;
            if (row < nrows) {
                *(float4*)&outA[(size_t)row*DIM + tx*4] =
                    make_float4(aA[r][0], aA[r][1], aA[r][2], aA[r][3]);
                *(float4*)&outB[(size_t)row*DIM + tx*4] =
                    make_float4(aB[r][0], aB[r][1], aB[r][2], aB[r][3]);
            }
        }
    }
}

// ---------------------------------------------------------------------------
// Warp-per-node CSR gather-accumulate. Each lane owns 2 of the 64 columns.
__device__ __forceinline__ float2 seg_accum(const float* __restrict__ m,
                                            int s, int e, int lane) {
    float2 acc = make_float2(0.f, 0.f);
    for (int base = s; base < e; base += 32) {
        int idx = base + lane;
        int2 rv = (idx < e) ? __ldg(&g_rec[idx]) : make_int2(0, 0);
        int cnt = min(32, e - base);
        int j = 0;
        for (; j + 4 <= cnt; j += 4) {
            int  s0 = __shfl_sync(0xffffffffu, rv.x, j+0);
            int  s1 = __shfl_sync(0xffffffffu, rv.x, j+1);
            int  s2 = __shfl_sync(0xffffffffu, rv.x, j+2);
            int  s3 = __shfl_sync(0xffffffffu, rv.x, j+3);
            float c0 = __int_as_float(__shfl_sync(0xffffffffu, rv.y, j+0));
            float c1 = __int_as_float(__shfl_sync(0xffffffffu, rv.y, j+1));
            float c2 = __int_as_float(__shfl_sync(0xffffffffu, rv.y, j+2));
            float c3 = __int_as_float(__shfl_sync(0xffffffffu, rv.y, j+3));
            float2 v0 = *(const float2*)&m[(size_t)s0*DIM + lane*2];
            float2 v1 = *(const float2*)&m[(size_t)s1*DIM + lane*2];
            float2 v2 = *(const float2*)&m[(size_t)s2*DIM + lane*2];
            float2 v3 = *(const float2*)&m[(size_t)s3*DIM + lane*2];
            acc.x += c0*v0.x; acc.y += c0*v0.y;
            acc.x += c1*v1.x; acc.y += c1*v1.y;
            acc.x += c2*v2.x; acc.y += c2*v2.y;
            acc.x += c3*v3.x; acc.y += c3*v3.y;
        }
        for (; j < cnt; j++) {
            int   sj = __shfl_sync(0xffffffffu, rv.x, j);
            float cj = __int_as_float(__shfl_sync(0xffffffffu, rv.y, j));
            float2 v = *(const float2*)&m[(size_t)sj*DIM + lane*2];
            acc.x += cj*v.x; acc.y += cj*v.y;
        }
    }
    return acc;
}

__global__ void __launch_bounds__(256) gather_kernel(
    const float* __restrict__ mA, int baseA,
    const float* __restrict__ mB, int baseB,
    float* __restrict__ outp, int nNodes)
{
    int w    = (blockIdx.x * blockDim.x + threadIdx.x) >> 5;
    int lane = threadIdx.x & 31;
    if (w >= nNodes) return;
    int sA = g_offs[baseA + w], eA = g_offs[baseA + w + 1];
    int sB = g_offs[baseB + w], eB = g_offs[baseB + w + 1];
    float2 a = seg_accum(mA, sA, eA, lane);
    float2 b = seg_accum(mB, sB, eB, lane);
    float2 r;
    r.x = fmaxf(a.x, 0.f) + fmaxf(b.x, 0.f);
    r.y = fmaxf(a.y, 0.f) + fmaxf(b.y, 0.f);
    *(float2*)&outp[(size_t)w*DIM + lane*2] = r;
}

// ---------------------------------------------------------------------------
// Epilogue: out = relu( in @ W )
__global__ void __launch_bounds__(256) aggr_kernel(
    const float* __restrict__ in, const float* __restrict__ W,
    float* __restrict__ out, int nrows)
{
    __shared__ float sW[64*64];
    __shared__ float sXT[64][68];

    int tid = threadIdx.x;
    for (int i = tid*4; i < 4096; i += 256*4)
        *(float4*)&sW[i] = *(const float4*)&W[i];

    int ntiles = (nrows + 63) >> 6;
    int tx = tid & 15;
    int ty = tid >> 4;

    for (int tile = blockIdx.x; tile < ntiles; tile += gridDim.x) {
        int row0 = tile << 6;
        __syncthreads();
        #pragma unroll
        for (int i = 0; i < 4; i++) {
            int q  = tid + i*256;
            int r  = q >> 4;
            int c4 = (q & 15) << 2;
            float4 v = make_float4(0.f,0.f,0.f,0.f);
            if (row0 + r < nrows)
                v = *(const float4*)&in[(size_t)(row0 + r)*DIM + c4];
            sXT[c4+0][r] = v.x; sXT[c4+1][r] = v.y; sXT[c4+2][r] = v.z; sXT[c4+3][r] = v.w;
        }
        __syncthreads();

        float acc4[4][4] = {};
        #pragma unroll
        for (int k = 0; k < 64; k++) {
            float4 xv = *(float4*)&sXT[k][ty*4];
            float4 w  = *(float4*)&sW[k*64 + tx*4];
            float xr[4] = {xv.x, xv.y, xv.z, xv.w};
            float wc[4] = {w.x, w.y, w.z, w.w};
            #pragma unroll
            for (int r = 0; r < 4; r++)
                #pragma unroll
                for (int c = 0; c < 4; c++)
                    acc4[r][c] += xr[r]*wc[c];
        }
        #pragma unroll
        for (int r = 0; r < 4; r++) {
            int row = row0 + ty*4 + r;
            if (row < nrows) {
                *(float4*)&out[(size_t)row*DIM + tx*4] =
                    make_float4(fmaxf(acc4[r][0],0.f), fmaxf(acc4[r][1],0.f),
                                fmaxf(acc4[r][2],0.f), fmaxf(acc4[r][3],0.f));
            }
        }
    }
}

// ---------------------------------------------------------------------------
extern "C" void kernel_launch(void* const* d_in, const int* in_sizes, int n_in,
                              void* d_out, int out_size) {
    const float* x0    = (const float*)d_in[0];
    const float* x1    = (const float*)d_in[1];
    const float* x2    = (const float*)d_in[2];
    const float* x3    = (const float*)d_in[3];
    const float* x4    = (const float*)d_in[4];
    const int*   adj0  = (const int*)  d_in[5];
    const float* adj0v = (const float*)d_in[6];
    const int*   adj1  = (const int*)  d_in[7];
    const float* adj1v = (const float*)d_in[8];
    const int*   inc   = (const int*)  d_in[9];
    const float* incv  = (const float*)d_in[10];
    const float* cci0  = (const float*)d_in[11];
    const float* cci1  = (const float*)d_in[12];
    const float* Whbs0 = (const float*)d_in[13];
    const float* a0    = (const float*)d_in[14];
    const float* Whbs1 = (const float*)d_in[15];
    const float* a1    = (const float*)d_in[16];
    const float* Ws    = (const float*)d_in[17];   // W_hbns_s
    const float* Wt    = (const float*)d_in[18];   // W_hbns_t
    const float* Wag0  = (const float*)d_in[19];
    const float* Wag1  = (const float*)d_in[20];
    float* out = (float*)d_out;

    float *pm, *psum;
    cudaGetSymbolAddress((void**)&pm,   g_m);
    cudaGetSymbolAddress((void**)&psum, g_sum);

    float* pm0 = pm;                        // x_0 @ W_hbs0
    float* pmt = pm + N0D;                  // x_0 @ W_hbns_t
    float* pm1 = pm + 2*(size_t)N0D;        // x_1 @ W_hbs1
    float* pms = pm + 2*(size_t)N0D + N1D;  // x_1 @ W_hbns_s

    float* sum0 = psum;                     // N0 rows
    float* sum1 = psum + N0D;               // N1 rows

    // binning chain
    zero_cnt_kernel<<<(NCNT + 255)/256, 256>>>();
    coef_kernel<<<((E0 + E1) + 255)/256, 256>>>(adj0v, cci0, a0, adj1v, cci1, a1);
    count_kernel<<<(ET + 255)/256, 256>>>(adj0, adj1, inc);
    scan_pass1<<<NB, 256>>>();
    scan_pass2<<<1, 512>>>();
    scan_pass3<<<NB, 256>>>();
    fill_kernel<<<(ET + 255)/256, 256>>>(adj0, adj1, inc, incv);

    // dense projections (keep m arrays hot in L2 for the gathers)
    gemm_dual_kernel<<<740, 128>>>(x0, Whbs0, Wt, pm0, pmt, N0);
    gemm_dual_kernel<<<740, 128>>>(x1, Whbs1, Ws, pm1, pms, N1);

    // atomic-free gather-accumulate (warp per node), fused relu+add
    gather_kernel<<<(N0*32 + 255)/256, 256>>>(pm0, B0, pms, B2, sum0, N0);
    gather_kernel<<<(N1*32 + 255)/256, 256>>>(pm1, B1, pmt, B3, sum1, N1);

    // epilogue GEMMs straight into d_out
    aggr_kernel<<<(N0 + 63)/64, 256>>>(sum0, Wag0, out, N0);
    aggr_kernel<<<(N1 + 63)/64, 256>>>(sum1, Wag1, out + (size_t)N0*DIM, N1);

    // passthrough outputs
    size_t off2 = (size_t)(N0 + N1)*DIM;
    size_t off3 = off2 + (size_t)N2*DIM;
    size_t off4 = off3 + (size_t)N3*DIM;
    cudaMemcpyAsync(out + off2, x2, (size_t)N2*DIM*sizeof(float), cudaMemcpyDeviceToDevice, 0);
    cudaMemcpyAsync(out + off3, x3, (size_t)N3*DIM*sizeof(float), cudaMemcpyDeviceToDevice, 0);
    cudaMemcpyAsync(out + off4, x4, (size_t)N4*DIM*sizeof(float), cudaMemcpyDeviceToDevice, 0);
}